// round 4
// baseline (speedup 1.0000x reference)
#include <cuda_runtime.h>

#define N_USERS 50000
#define N_ENT   150000
#define NN      200000
#define NE      2000000
#define NB      8192
#define TOT     176   // 64 + 64 + 32 + 16
#define NCHUNK  256
#define CHSZ    782   // ceil(NN/256)

// Scratch (allocation-free rule: __device__ globals)
__device__ float g_ego [NN * 64];
__device__ float g_ego2[NN * 64];
__device__ float g_all [NN * TOT];
__device__ int   g_deg   [NN];
__device__ int   g_off   [NN];
__device__ int   g_rowptr[NN];
__device__ int   g_csum  [NCHUNK];
__device__ int   g_coff  [NCHUNK];
__device__ int2  g_edge  [NE];      // (col, bitcast(val)) grouped by row

// ---------------------------------------------------------------------------
// packed f32x2 helpers (FFMA2 only reachable via PTX)
__device__ __forceinline__ unsigned long long pk2(float a, float b) {
    unsigned long long r;
    asm("mov.b64 %0, {%1, %2};" : "=l"(r) : "f"(a), "f"(b));
    return r;
}
__device__ __forceinline__ void ffma2(unsigned long long& d,
                                      unsigned long long a, unsigned long long b) {
    asm("fma.rn.f32x2 %0, %1, %2, %0;" : "+l"(d) : "l"(a), "l"(b));
}
__device__ __forceinline__ float2 upk2(unsigned long long v) {
    float x, y;
    asm("mov.b64 {%0, %1}, %2;" : "=f"(x), "=f"(y) : "l"(v));
    return make_float2(x, y);
}

// ---------------------------------------------------------------------------
__global__ void k_init(const float* __restrict__ ue, const float* __restrict__ ee) {
    int i = blockIdx.x * blockDim.x + threadIdx.x;   // over NN*16
    if (i >= NN * 16) return;
    int n = i >> 4, c = i & 15;
    float4 v = (n < N_USERS)
        ? ((const float4*)ue)[(size_t)n * 16 + c]
        : ((const float4*)ee)[(size_t)(n - N_USERS) * 16 + c];
    ((float4*)g_ego)[i] = v;
    ((float4*)(g_all + (size_t)n * TOT))[c] = v;
}

__global__ void k_zero2(int* __restrict__ a, int* __restrict__ b, int n) {
    int i = blockIdx.x * blockDim.x + threadIdx.x;
    if (i < n) { a[i] = 0; b[i] = 0; }
}

// ---------------------------------------------------------------------------
// CSR build
__global__ void k_hist(const int* __restrict__ rows) {
    int e = blockIdx.x * blockDim.x + threadIdx.x;
    if (e < NE) atomicAdd(&g_deg[rows[e]], 1);
}

__global__ void k_csum() {  // 256 blocks x 256 threads: chunk sums
    __shared__ int s[256];
    int b = blockIdx.x, tid = threadIdx.x;
    int beg = b * CHSZ, end = min(beg + CHSZ, NN);
    int acc = 0;
    for (int i = beg + tid; i < end; i += 256) acc += g_deg[i];
    s[tid] = acc; __syncthreads();
    for (int o = 128; o > 0; o >>= 1) { if (tid < o) s[tid] += s[tid + o]; __syncthreads(); }
    if (tid == 0) g_csum[b] = s[0];
}

__global__ void k_scan256() {  // 1 block: exclusive scan of chunk sums
    __shared__ int s[256];
    int tid = threadIdx.x;
    int v = g_csum[tid];
    s[tid] = v; __syncthreads();
    for (int o = 1; o < 256; o <<= 1) {
        int t = (tid >= o) ? s[tid - o] : 0;
        __syncthreads(); s[tid] += t; __syncthreads();
    }
    g_coff[tid] = s[tid] - v;
}

__global__ void k_rowptr() {  // 256 blocks: scan within chunk
    __shared__ int s[256];
    __shared__ int stot;
    int b = blockIdx.x, tid = threadIdx.x;
    int beg = b * CHSZ, end = min(beg + CHSZ, NN);
    int running = g_coff[b];
    for (int t = beg; t < end; t += 256) {
        int idx = t + tid;
        int v = (idx < end) ? g_deg[idx] : 0;
        s[tid] = v; __syncthreads();
        for (int o = 1; o < 256; o <<= 1) {
            int u = (tid >= o) ? s[tid - o] : 0;
            __syncthreads(); s[tid] += u; __syncthreads();
        }
        if (idx < end) g_rowptr[idx] = running + s[tid] - v;
        if (tid == 255) stot = s[255];
        __syncthreads();
        running += stot;
        __syncthreads();
    }
}

__global__ void k_place(const int* __restrict__ rows, const int* __restrict__ cols,
                        const float* __restrict__ vals) {
    int e = blockIdx.x * blockDim.x + threadIdx.x;
    if (e >= NE) return;
    int r = rows[e];
    int p = g_rowptr[r] + atomicAdd(&g_off[r], 1);
    g_edge[p] = make_int2(cols[e], __float_as_int(vals[e]));
}

// ---------------------------------------------------------------------------
// Fused: side-gather + GC/BI transform + l2norm. One warp per node.
//
// Gather: warp split into EPG groups of V4 lanes; each group processes one edge
// at a time (uniform edge-header load, one float4 gather per lane). Groups are
// reduced with shfl_xor at the end.
//
// Matmul: lanes 0-15 = GC, 16-31 = BI. Each lane owns 4 output columns;
// weights read from smem as ulonglong2 and accumulated with packed FFMA2.
template<int DIN, int DOUT, int OFF>
__global__ void k_layer(const float* __restrict__ Wg, const float* __restrict__ bg,
                        const float* __restrict__ Wb, const float* __restrict__ bb,
                        const float* __restrict__ src, float* __restrict__ dst) {
    constexpr int V4  = DIN / 4;        // float4 per input row (16 or 8)
    constexpr int EPG = 32 / V4;        // edge groups per warp (2 or 4)
    constexpr int LPM = DOUT / 4;       // active lanes per matrix (16, 8, 4)
    constexpr int WPB = 8;
    __shared__ __align__(16) float sW[2 * DIN * DOUT];
    __shared__ __align__(16) float sB[2 * DOUT];
    __shared__ __align__(16) float sx[WPB][2][DIN];

    int tid = threadIdx.x;
    for (int i = tid; i < DIN * DOUT; i += blockDim.x) { sW[i] = Wg[i]; sW[DIN * DOUT + i] = Wb[i]; }
    for (int i = tid; i < DOUT; i += blockDim.x)       { sB[i] = bg[i]; sB[DOUT + i] = bb[i]; }
    __syncthreads();

    int w = tid >> 5, lane = tid & 31;
    int grp = lane / V4;                // edge group id
    int sub = lane & (V4 - 1);          // float4 index within row
    int h  = lane >> 4;                 // 0 = GC, 1 = BI (matmul phase)
    int jl = lane & 15;
    int jc = (jl < LPM) ? jl : 0;
    const float* wbase = sW + h * DIN * DOUT;
    const float* xbase = &sx[w][h][0];

    for (int n = blockIdx.x * WPB + w; n < NN; n += gridDim.x * WPB) {
        // ---- gather: acc = sum_e val_e * src[col_e] ----
        float4 acc = make_float4(0.f, 0.f, 0.f, 0.f);
        int s0 = g_rowptr[n], cnt = g_deg[n];
        for (int e = grp; e < cnt; e += EPG) {
            int2 ev = g_edge[s0 + e];                     // uniform per group
            float v = __int_as_float(ev.y);
            float4 x = ((const float4*)src)[(size_t)ev.x * V4 + sub];
            acc.x = fmaf(v, x.x, acc.x);
            acc.y = fmaf(v, x.y, acc.y);
            acc.z = fmaf(v, x.z, acc.z);
            acc.w = fmaf(v, x.w, acc.w);
        }
        #pragma unroll
        for (int off = V4; off < 32; off <<= 1) {
            acc.x += __shfl_xor_sync(0xffffffffu, acc.x, off);
            acc.y += __shfl_xor_sync(0xffffffffu, acc.y, off);
            acc.z += __shfl_xor_sync(0xffffffffu, acc.z, off);
            acc.w += __shfl_xor_sync(0xffffffffu, acc.w, off);
        }
        if (grp == 0) {
            float4 er = ((const float4*)src)[(size_t)n * V4 + sub];
            float4 s1v = make_float4(er.x + acc.x, er.y + acc.y, er.z + acc.z, er.w + acc.w);
            float4 s2v = make_float4(er.x * acc.x, er.y * acc.y, er.z * acc.z, er.w * acc.w);
            ((float4*)&sx[w][0][0])[sub] = s1v;
            ((float4*)&sx[w][1][0])[sub] = s2v;
        }
        __syncwarp();

        // ---- matmul with packed FFMA2 ----
        unsigned long long p01 = 0ull, p23 = 0ull;   // bit pattern of (0,0)
        #pragma unroll
        for (int k4 = 0; k4 < DIN; k4 += 4) {
            float4 xv = *(const float4*)(xbase + k4);
            #pragma unroll
            for (int i = 0; i < 4; i++) {
                ulonglong2 wv = ((const ulonglong2*)(wbase + (k4 + i) * DOUT))[jc];
                float xk = (&xv.x)[i];
                unsigned long long xx = pk2(xk, xk);
                ffma2(p01, xx, wv.x);
                ffma2(p23, xx, wv.y);
            }
        }
        float2 a01 = upk2(p01), a23 = upk2(p23);
        float4 bv = ((const float4*)(sB + h * DOUT))[jc];
        float4 v;
        v.x = a01.x + bv.x; v.x = v.x > 0.f ? v.x : 0.01f * v.x;
        v.y = a01.y + bv.y; v.y = v.y > 0.f ? v.y : 0.01f * v.y;
        v.z = a23.x + bv.z; v.z = v.z > 0.f ? v.z : 0.01f * v.z;
        v.w = a23.y + bv.w; v.w = v.w > 0.f ? v.w : 0.01f * v.w;
        // combine GC + BI halves
        float4 o;
        o.x = v.x + __shfl_xor_sync(0xffffffffu, v.x, 16);
        o.y = v.y + __shfl_xor_sync(0xffffffffu, v.y, 16);
        o.z = v.z + __shfl_xor_sync(0xffffffffu, v.z, 16);
        o.w = v.w + __shfl_xor_sync(0xffffffffu, v.w, 16);
        float ss = o.x * o.x + o.y * o.y + o.z * o.z + o.w * o.w;
        #pragma unroll
        for (int off = LPM / 2; off > 0; off >>= 1)
            ss += __shfl_xor_sync(0xffffffffu, ss, off);
        float inv = 1.0f / fmaxf(sqrtf(ss), 1e-12f);
        if (h == 0 && jl < LPM) {
            ((float4*)(dst + (size_t)n * DOUT))[jl] = o;
            float4 on = make_float4(o.x * inv, o.y * inv, o.z * inv, o.w * inv);
            ((float4*)(g_all + (size_t)n * TOT + OFF))[jl] = on;
        }
        __syncwarp();
    }
}

// ---------------------------------------------------------------------------
__global__ void k_score(const int* __restrict__ users, const int* __restrict__ pos,
                        const int* __restrict__ neg, float* __restrict__ out) {
    int wid  = (blockIdx.x * blockDim.x + threadIdx.x) >> 5;
    int lane = threadIdx.x & 31;
    if (wid >= NB) return;
    const float* u = g_all + (size_t)users[wid] * TOT;
    const float* p = g_all + (size_t)(N_USERS + pos[wid]) * TOT;
    const float* q = g_all + (size_t)(N_USERS + neg[wid]) * TOT;
    float sp = 0.f, sn = 0.f;
    #pragma unroll
    for (int k = lane; k < TOT; k += 32) {
        float uv = u[k];
        sp += uv * p[k];
        sn += uv * q[k];
    }
    #pragma unroll
    for (int o = 16; o > 0; o >>= 1) {
        sp += __shfl_xor_sync(0xffffffffu, sp, o);
        sn += __shfl_xor_sync(0xffffffffu, sn, o);
    }
    if (lane == 0) { out[2 * wid] = sp; out[2 * wid + 1] = sn; }
}

// ---------------------------------------------------------------------------
extern "C" void kernel_launch(void* const* d_in, const int* in_sizes, int n_in,
                              void* d_out, int out_size) {
    const int*   users = (const int*)  d_in[0];
    const int*   pos   = (const int*)  d_in[1];
    const int*   neg   = (const int*)  d_in[2];
    const int*   rows  = (const int*)  d_in[3];
    const int*   cols  = (const int*)  d_in[4];
    const float* vals  = (const float*)d_in[5];
    const float* ue    = (const float*)d_in[6];
    const float* ee    = (const float*)d_in[7];
    const float* W[3][4];
    for (int l = 0; l < 3; l++)
        for (int j = 0; j < 4; j++)
            W[l][j] = (const float*)d_in[8 + 4 * l + j];

    float *p_ego, *p_ego2;
    int *p_deg, *p_off;
    cudaGetSymbolAddress((void**)&p_ego,  g_ego);
    cudaGetSymbolAddress((void**)&p_ego2, g_ego2);
    cudaGetSymbolAddress((void**)&p_deg,  g_deg);
    cudaGetSymbolAddress((void**)&p_off,  g_off);

    const int TB = 256;

    k_init<<<(NN * 16 + TB - 1) / TB, TB>>>(ue, ee);

    // CSR build
    k_zero2<<<(NN + TB - 1) / TB, TB>>>(p_deg, p_off, NN);
    k_hist<<<(NE + TB - 1) / TB, TB>>>(rows);
    k_csum<<<NCHUNK, 256>>>();
    k_scan256<<<1, 256>>>();
    k_rowptr<<<NCHUNK, 256>>>();
    k_place<<<(NE + TB - 1) / TB, TB>>>(rows, cols, vals);

    // Layers (fused gather + transform + l2norm)
    k_layer<64, 64,  64><<<888, TB>>>(W[0][0], W[0][1], W[0][2], W[0][3], p_ego,  p_ego2);
    k_layer<64, 32, 128><<<888, TB>>>(W[1][0], W[1][1], W[1][2], W[1][3], p_ego2, p_ego);
    k_layer<32, 16, 160><<<888, TB>>>(W[2][0], W[2][1], W[2][2], W[2][3], p_ego,  p_ego2);

    k_score<<<(NB * 32 + TB - 1) / TB, TB>>>(users, pos, neg, (float*)d_out);
}

// round 5
// speedup vs baseline: 1.5075x; 1.5075x over previous
#include <cuda_runtime.h>

#define N_USERS 50000
#define N_ENT   150000
#define NN      200000
#define NE      2000000
#define NB      8192
#define TOT     176   // 64 + 64 + 32 + 16
#define NCHUNK  256
#define CHSZ    782   // ceil(NN/256)

// Scratch (allocation-free rule: __device__ globals)
__device__ float g_ego [NN * 64];
__device__ float g_ego2[NN * 64];
__device__ float g_all [NN * TOT];
__device__ int   g_deg   [NN];
__device__ int   g_off   [NN];
__device__ int   g_rowptr[NN];
__device__ int   g_csum  [NCHUNK];
__device__ int   g_coff  [NCHUNK];
__device__ int2  g_edge  [NE];      // (col, bitcast(val)) grouped by row

// ---------------------------------------------------------------------------
// packed f32x2 helpers (FFMA2 only reachable via PTX)
__device__ __forceinline__ unsigned long long pk2(float a) {
    unsigned long long r;
    asm("mov.b64 %0, {%1, %1};" : "=l"(r) : "f"(a));
    return r;
}
__device__ __forceinline__ void ffma2(unsigned long long& d,
                                      unsigned long long a, unsigned long long b) {
    asm("fma.rn.f32x2 %0, %1, %2, %0;" : "+l"(d) : "l"(a), "l"(b));
}
__device__ __forceinline__ float2 upk2(unsigned long long v) {
    float x, y;
    asm("mov.b64 {%0, %1}, %2;" : "=f"(x), "=f"(y) : "l"(v));
    return make_float2(x, y);
}

// ---------------------------------------------------------------------------
__global__ void k_init(const float* __restrict__ ue, const float* __restrict__ ee) {
    int i = blockIdx.x * blockDim.x + threadIdx.x;   // over NN*16
    if (i >= NN * 16) return;
    int n = i >> 4, c = i & 15;
    float4 v = (n < N_USERS)
        ? ((const float4*)ue)[(size_t)n * 16 + c]
        : ((const float4*)ee)[(size_t)(n - N_USERS) * 16 + c];
    ((float4*)g_ego)[i] = v;
    ((float4*)(g_all + (size_t)n * TOT))[c] = v;
}

__global__ void k_zero2(int* __restrict__ a, int* __restrict__ b, int n) {
    int i = blockIdx.x * blockDim.x + threadIdx.x;
    if (i < n) { a[i] = 0; b[i] = 0; }
}

// ---------------------------------------------------------------------------
// CSR build
__global__ void k_hist(const int* __restrict__ rows) {
    int e = blockIdx.x * blockDim.x + threadIdx.x;
    if (e < NE) atomicAdd(&g_deg[rows[e]], 1);
}

__global__ void k_csum() {  // 256 blocks x 256 threads: chunk sums
    __shared__ int s[256];
    int b = blockIdx.x, tid = threadIdx.x;
    int beg = b * CHSZ, end = min(beg + CHSZ, NN);
    int acc = 0;
    for (int i = beg + tid; i < end; i += 256) acc += g_deg[i];
    s[tid] = acc; __syncthreads();
    for (int o = 128; o > 0; o >>= 1) { if (tid < o) s[tid] += s[tid + o]; __syncthreads(); }
    if (tid == 0) g_csum[b] = s[0];
}

__global__ void k_scan256() {  // 1 block: exclusive scan of chunk sums
    __shared__ int s[256];
    int tid = threadIdx.x;
    int v = g_csum[tid];
    s[tid] = v; __syncthreads();
    for (int o = 1; o < 256; o <<= 1) {
        int t = (tid >= o) ? s[tid - o] : 0;
        __syncthreads(); s[tid] += t; __syncthreads();
    }
    g_coff[tid] = s[tid] - v;
}

__global__ void k_rowptr() {  // 256 blocks: scan within chunk
    __shared__ int s[256];
    __shared__ int stot;
    int b = blockIdx.x, tid = threadIdx.x;
    int beg = b * CHSZ, end = min(beg + CHSZ, NN);
    int running = g_coff[b];
    for (int t = beg; t < end; t += 256) {
        int idx = t + tid;
        int v = (idx < end) ? g_deg[idx] : 0;
        s[tid] = v; __syncthreads();
        for (int o = 1; o < 256; o <<= 1) {
            int u = (tid >= o) ? s[tid - o] : 0;
            __syncthreads(); s[tid] += u; __syncthreads();
        }
        if (idx < end) g_rowptr[idx] = running + s[tid] - v;
        if (tid == 255) stot = s[255];
        __syncthreads();
        running += stot;
        __syncthreads();
    }
}

__global__ void k_place(const int* __restrict__ rows, const int* __restrict__ cols,
                        const float* __restrict__ vals) {
    int e = blockIdx.x * blockDim.x + threadIdx.x;
    if (e >= NE) return;
    int r = rows[e];
    int p = g_rowptr[r] + atomicAdd(&g_off[r], 1);
    g_edge[p] = make_int2(cols[e], __float_as_int(vals[e]));
}

// ---------------------------------------------------------------------------
// Fused: side-gather + GC/BI transform + l2norm.
// One warp handles NT=4 nodes: gathers them (round-2 proven shuffle-broadcast
// loop), then a single node-tiled matmul pass so every weight LDS.128 is
// amortized over 4 nodes (smem traffic /4). Matmul uses packed FFMA2.
template<int DIN, int DOUT, int OFF>
__global__ void k_layer(const float* __restrict__ Wg, const float* __restrict__ bg,
                        const float* __restrict__ Wb, const float* __restrict__ bb,
                        const float* __restrict__ src, float* __restrict__ dst) {
    constexpr int KC  = DIN / 32;
    constexpr int LPM = DOUT / 4;       // active lanes per matrix
    constexpr int NT  = 4;              // nodes per warp per matmul pass
    constexpr int WPB = 6;
    __shared__ __align__(16) float sW[2 * DIN * DOUT];
    __shared__ __align__(16) float sB[2 * DOUT];
    __shared__ __align__(16) float sx[WPB][NT][2][DIN];

    int tid = threadIdx.x;
    for (int i = tid; i < DIN * DOUT; i += blockDim.x) { sW[i] = Wg[i]; sW[DIN * DOUT + i] = Wb[i]; }
    for (int i = tid; i < DOUT; i += blockDim.x)       { sB[i] = bg[i]; sB[DOUT + i] = bb[i]; }
    __syncthreads();

    int w = tid >> 5, lane = tid & 31;
    int h  = lane >> 4;                 // 0 = GC, 1 = BI
    int jl = lane & 15;
    int jc = (jl < LPM) ? jl : 0;
    const float* wbase = sW + h * DIN * DOUT;

    for (int nb = (blockIdx.x * WPB + w) * NT; nb < NN; nb += gridDim.x * WPB * NT) {
        // ---- gather NT nodes into sx (round-2 structure) ----
        #pragma unroll
        for (int t = 0; t < NT; t++) {
            int n = nb + t;
            if (n >= NN) break;
            float er[KC], acc[KC];
            #pragma unroll
            for (int c = 0; c < KC; c++) {
                er[c]  = src[(size_t)n * DIN + lane + 32 * c];
                acc[c] = 0.f;
            }
            int s0 = g_rowptr[n], cnt = g_deg[n];
            for (int base = 0; base < cnt; base += 32) {
                int2 ev = make_int2(0, 0);
                if (base + lane < cnt) ev = g_edge[s0 + base + lane];
                int vn = min(32, cnt - base);
                for (int m = 0; m < vn; m++) {
                    int   col = __shfl_sync(0xffffffffu, ev.x, m);
                    float val = __int_as_float(__shfl_sync(0xffffffffu, ev.y, m));
                    #pragma unroll
                    for (int c = 0; c < KC; c++)
                        acc[c] = fmaf(val, src[(size_t)col * DIN + lane + 32 * c], acc[c]);
                }
            }
            #pragma unroll
            for (int c = 0; c < KC; c++) {
                int k = lane + 32 * c;
                sx[w][t][0][k] = er[c] + acc[c];
                sx[w][t][1][k] = er[c] * acc[c];
            }
        }
        __syncwarp();

        // ---- node-tiled matmul with packed FFMA2 ----
        unsigned long long p01[NT], p23[NT];
        #pragma unroll
        for (int t = 0; t < NT; t++) { p01[t] = 0ull; p23[t] = 0ull; }

        #pragma unroll
        for (int k4 = 0; k4 < DIN; k4 += 4) {
            float4 xv[NT];
            #pragma unroll
            for (int t = 0; t < NT; t++)
                xv[t] = *(const float4*)(&sx[w][t][h][k4]);
            #pragma unroll
            for (int i = 0; i < 4; i++) {
                ulonglong2 wv = ((const ulonglong2*)(wbase + (k4 + i) * DOUT))[jc];
                #pragma unroll
                for (int t = 0; t < NT; t++) {
                    unsigned long long xx = pk2((&xv[t].x)[i]);
                    ffma2(p01[t], xx, wv.x);
                    ffma2(p23[t], xx, wv.y);
                }
            }
        }

        float4 bv = ((const float4*)(sB + h * DOUT))[jc];
        #pragma unroll
        for (int t = 0; t < NT; t++) {
            int n = nb + t;
            float2 a01 = upk2(p01[t]), a23 = upk2(p23[t]);
            float4 v;
            v.x = a01.x + bv.x; v.x = v.x > 0.f ? v.x : 0.01f * v.x;
            v.y = a01.y + bv.y; v.y = v.y > 0.f ? v.y : 0.01f * v.y;
            v.z = a23.x + bv.z; v.z = v.z > 0.f ? v.z : 0.01f * v.z;
            v.w = a23.y + bv.w; v.w = v.w > 0.f ? v.w : 0.01f * v.w;
            float4 o;
            o.x = v.x + __shfl_xor_sync(0xffffffffu, v.x, 16);
            o.y = v.y + __shfl_xor_sync(0xffffffffu, v.y, 16);
            o.z = v.z + __shfl_xor_sync(0xffffffffu, v.z, 16);
            o.w = v.w + __shfl_xor_sync(0xffffffffu, v.w, 16);
            float ss = o.x * o.x + o.y * o.y + o.z * o.z + o.w * o.w;
            #pragma unroll
            for (int off = LPM / 2; off > 0; off >>= 1)
                ss += __shfl_xor_sync(0xffffffffu, ss, off);
            float inv = 1.0f / fmaxf(sqrtf(ss), 1e-12f);
            if (n < NN && h == 0 && jl < LPM) {
                ((float4*)(dst + (size_t)n * DOUT))[jl] = o;
                float4 on = make_float4(o.x * inv, o.y * inv, o.z * inv, o.w * inv);
                ((float4*)(g_all + (size_t)n * TOT + OFF))[jl] = on;
            }
        }
        __syncwarp();
    }
}

// ---------------------------------------------------------------------------
__global__ void k_score(const int* __restrict__ users, const int* __restrict__ pos,
                        const int* __restrict__ neg, float* __restrict__ out) {
    int wid  = (blockIdx.x * blockDim.x + threadIdx.x) >> 5;
    int lane = threadIdx.x & 31;
    if (wid >= NB) return;
    const float* u = g_all + (size_t)users[wid] * TOT;
    const float* p = g_all + (size_t)(N_USERS + pos[wid]) * TOT;
    const float* q = g_all + (size_t)(N_USERS + neg[wid]) * TOT;
    float sp = 0.f, sn = 0.f;
    #pragma unroll
    for (int k = lane; k < TOT; k += 32) {
        float uv = u[k];
        sp += uv * p[k];
        sn += uv * q[k];
    }
    #pragma unroll
    for (int o = 16; o > 0; o >>= 1) {
        sp += __shfl_xor_sync(0xffffffffu, sp, o);
        sn += __shfl_xor_sync(0xffffffffu, sn, o);
    }
    if (lane == 0) { out[2 * wid] = sp; out[2 * wid + 1] = sn; }
}

// ---------------------------------------------------------------------------
extern "C" void kernel_launch(void* const* d_in, const int* in_sizes, int n_in,
                              void* d_out, int out_size) {
    const int*   users = (const int*)  d_in[0];
    const int*   pos   = (const int*)  d_in[1];
    const int*   neg   = (const int*)  d_in[2];
    const int*   rows  = (const int*)  d_in[3];
    const int*   cols  = (const int*)  d_in[4];
    const float* vals  = (const float*)d_in[5];
    const float* ue    = (const float*)d_in[6];
    const float* ee    = (const float*)d_in[7];
    const float* W[3][4];
    for (int l = 0; l < 3; l++)
        for (int j = 0; j < 4; j++)
            W[l][j] = (const float*)d_in[8 + 4 * l + j];

    float *p_ego, *p_ego2;
    int *p_deg, *p_off;
    cudaGetSymbolAddress((void**)&p_ego,  g_ego);
    cudaGetSymbolAddress((void**)&p_ego2, g_ego2);
    cudaGetSymbolAddress((void**)&p_deg,  g_deg);
    cudaGetSymbolAddress((void**)&p_off,  g_off);

    const int TB = 256;
    const int TBL = 192;   // 6 warps per block for k_layer

    k_init<<<(NN * 16 + TB - 1) / TB, TB>>>(ue, ee);

    // CSR build
    k_zero2<<<(NN + TB - 1) / TB, TB>>>(p_deg, p_off, NN);
    k_hist<<<(NE + TB - 1) / TB, TB>>>(rows);
    k_csum<<<NCHUNK, 256>>>();
    k_scan256<<<1, 256>>>();
    k_rowptr<<<NCHUNK, 256>>>();
    k_place<<<(NE + TB - 1) / TB, TB>>>(rows, cols, vals);

    // Layers (fused gather + node-tiled transform + l2norm)
    k_layer<64, 64,  64><<<740, TBL>>>(W[0][0], W[0][1], W[0][2], W[0][3], p_ego,  p_ego2);
    k_layer<64, 32, 128><<<740, TBL>>>(W[1][0], W[1][1], W[1][2], W[1][3], p_ego2, p_ego);
    k_layer<32, 16, 160><<<740, TBL>>>(W[2][0], W[2][1], W[2][2], W[2][3], p_ego,  p_ego2);

    k_score<<<(NB * 32 + TB - 1) / TB, TB>>>(users, pos, neg, (float*)d_out);
}